// round 1
// baseline (speedup 1.0000x reference)
#include <cuda_runtime.h>

// Problem constants
#define Bsz   16
#define Lseq  4096
#define Dd    512
#define SPB   8          // sequences (d-lanes) per block
#define CH    64         // chunk length
#define NCH   64         // chunks per sequence (CH*NCH == Lseq)
#define NTH   512        // SPB * NCH / ... = 8 seq * 64 chunks = 512 threads
#define CPAD  65         // padded chunk stride in smem (conflict-free)
#define SEQSTR (NCH*CPAD + 4)   // 4164 floats per sequence row

// Dynamic smem layout (floats):
//  Y  : SPB*SEQSTR        (x -> p0_fwd -> y_fwd -> p0_bwd, in place)
//  RR : 2*CH              (first row of A^(i+1), i=0..63)  [float2]
//  MM : 4                 (A^64 full matrix)
//  VV : SPB*NCH*2         (chunk end-states, zero-init)
//  SS : SPB*NCH*2         (chunk start-states after combine)
//  CV : 2*SPB             (fwd/bwd boundary constants c)
#define SMEM_FLOATS (SPB*SEQSTR + 2*CH + 4 + SPB*NCH*2 + SPB*NCH*2 + 2*SPB)

__global__ void __launch_bounds__(NTH, 1)
iir_filtfilt_kernel(const float* __restrict__ x,
                    const float* __restrict__ bc,
                    const float* __restrict__ am,
                    float* __restrict__ out)
{
    extern __shared__ float sm[];
    float*  Y  = sm;                              // SPB*SEQSTR
    float2* RR = (float2*)(Y + SPB * SEQSTR);     // CH entries
    float*  MM = (float*)(RR + CH);               // 4
    float*  VV = MM + 4;                          // SPB*NCH*2
    float*  SS = VV + SPB * NCH * 2;              // SPB*NCH*2
    float*  CV = SS + SPB * NCH * 2;              // 2*SPB

    const int tid = threadIdx.x;
    const int seq = tid & (SPB - 1);
    const int ch  = tid >> 3;                     // 0..63
    const int b   = blockIdx.x >> 6;              // / (Dd/SPB)
    const int d0  = (blockIdx.x & 63) * SPB;

    const float b0  = bc[0], b1 = bc[1], b2 = bc[2];
    const float na1 = am[0], na2 = am[1];         // A row0 = (-a1, -a2)
    const float bsum = b0 + b1 + b2;

    // Thread 0: coefficient table  RR[i] = row0(A^(i+1)),  MM = A^64.
    if (tid == 0) {
        float p00 = na1, p01 = na2, p10 = 1.f, p11 = 0.f;   // A^1
        RR[0] = make_float2(p00, p01);
        for (int i = 1; i < CH; ++i) {
            float q00 = fmaf(na1, p00, na2 * p10);
            float q01 = fmaf(na1, p01, na2 * p11);
            p10 = p00; p11 = p01;
            p00 = q00; p01 = q01;
            RR[i] = make_float2(p00, p01);
        }
        MM[0] = p00; MM[1] = p01; MM[2] = p10; MM[3] = p11;
    }

    // Stage x -> smem, transposed to [seq][l] with conflict-free padding.
    {
        const float* xb = x + ((size_t)b * Lseq) * Dd + d0;
        const int dl = tid & 7;
        const int l0 = tid >> 3;          // 0..63
        float* yd = Y + dl * SEQSTR;
        #pragma unroll 8
        for (int k = 0; k < Lseq; k += 64) {
            int l = l0 + k;
            yd[l + (l >> 6)] = xb[(size_t)l * Dd + dl];
        }
    }
    __syncthreads();

    const int base = seq * SEQSTR + ch * CPAD;

    // Copy own chunk of x to registers (+ 2-element halo), record fwd init c.
    float xr[CH];
    #pragma unroll
    for (int i = 0; i < CH; ++i) xr[i] = Y[base + i];
    float xm1, xm2;
    if (ch == 0) {
        xm1 = xr[0]; xm2 = xr[0];
        CV[seq] = bsum * xr[0];           // c_fwd = (b0+b1+b2)*x[0]
    } else {
        xm1 = Y[base - 2];                // prev chunk, i=63
        xm2 = Y[base - 3];                // prev chunk, i=62
    }
    __syncthreads();                      // all Y(x) reads done before overwrite

    // Forward phase-1: zero-init scan of own chunk, particular p0 -> Y.
    float s0 = 0.f, s1 = 0.f;
    #pragma unroll
    for (int i = 0; i < CH; ++i) {
        float bx = fmaf(b2, xm2, fmaf(b1, xm1, b0 * xr[i]));
        xm2 = xm1; xm1 = xr[i];
        float ns = fmaf(na1, s0, fmaf(na2, s1, bx));
        s1 = s0; s0 = ns;
        Y[base + i] = ns;
    }
    {
        int vi = (seq * NCH + ch) * 2;
        VV[vi] = s0; VV[vi + 1] = s1;
    }
    __syncthreads();

    // Forward chunk-combine (one thread per sequence).
    if (tid < SPB) {
        float m00 = MM[0], m01 = MM[1], m10 = MM[2], m11 = MM[3];
        float c  = CV[tid];
        float t0 = c, t1 = c;
        int bi = tid * NCH * 2;
        for (int j = 0; j < NCH; ++j) {
            float v0 = VV[bi + 2*j], v1 = VV[bi + 2*j + 1];
            SS[bi + 2*j] = t0; SS[bi + 2*j + 1] = t1;
            float u0 = fmaf(m00, t0, fmaf(m01, t1, v0));
            float u1 = fmaf(m10, t0, fmaf(m11, t1, v1));
            t0 = u0; t1 = u1;
        }
    }
    __syncthreads();

    // Forward fix-up: y[t] = p0[t] + row0(A^(i+1)) . s_start  (in place in Y).
    {
        int si = (seq * NCH + ch) * 2;
        float ss0 = SS[si], ss1 = SS[si + 1];
        float last = 0.f;
        #pragma unroll 8
        for (int i = 0; i < CH; ++i) {
            float2 r = RR[i];
            float yv = fmaf(r.x, ss0, fmaf(r.y, ss1, Y[base + i]));
            Y[base + i] = yv;
            last = yv;
        }
        if (ch == NCH - 1) CV[SPB + seq] = bsum * last;   // c_bwd = bsum*y[L-1]
    }
    __syncthreads();

    // Backward halo: y[t+1], y[t+2] at the chunk's high edge (clamped at L-1).
    float yp1, yp2;
    if (ch == NCH - 1) { float e = Y[base + CH - 1]; yp1 = e; yp2 = e; }
    else               { yp1 = Y[base + CPAD]; yp2 = Y[base + CPAD + 1]; }
    __syncthreads();                      // halos read before overwrite

    // Backward phase-1: zero-init anticausal scan, p0_bwd -> Y (in place).
    s0 = 0.f; s1 = 0.f;
    #pragma unroll 8
    for (int i = CH - 1; i >= 0; --i) {
        float yv = Y[base + i];
        float bx = fmaf(b2, yp2, fmaf(b1, yp1, b0 * yv));
        yp2 = yp1; yp1 = yv;
        float ns = fmaf(na1, s0, fmaf(na2, s1, bx));
        s1 = s0; s0 = ns;
        Y[base + i] = ns;
    }
    {
        int vi = (seq * NCH + ch) * 2;
        VV[vi] = s0; VV[vi + 1] = s1;
    }
    __syncthreads();

    // Backward chunk-combine (reversed order).
    if (tid < SPB) {
        float m00 = MM[0], m01 = MM[1], m10 = MM[2], m11 = MM[3];
        float c  = CV[SPB + tid];
        float t0 = c, t1 = c;
        int bi = tid * NCH * 2;
        for (int j = NCH - 1; j >= 0; --j) {
            float v0 = VV[bi + 2*j], v1 = VV[bi + 2*j + 1];
            SS[bi + 2*j] = t0; SS[bi + 2*j + 1] = t1;
            float u0 = fmaf(m00, t0, fmaf(m01, t1, v0));
            float u1 = fmaf(m10, t0, fmaf(m11, t1, v1));
            t0 = u0; t1 = u1;
        }
    }
    __syncthreads();

    // Final fix-up + stores: seas = p0_bwd + row0(A^(64-i)) . ss ; trend = x - seas.
    {
        int si = (seq * NCH + ch) * 2;
        float ss0 = SS[si], ss1 = SS[si + 1];
        size_t obase = ((size_t)b * Lseq + (size_t)ch * CH) * Dd + d0 + seq;
        float* outs = out;
        float* outt = out + (size_t)Bsz * Lseq * Dd;
        #pragma unroll
        for (int i = 0; i < CH; ++i) {
            float2 r = RR[CH - 1 - i];    // backward step index = 63 - i
            float se = fmaf(r.x, ss0, fmaf(r.y, ss1, Y[base + i]));
            size_t o = obase + (size_t)i * Dd;
            outs[o] = se;
            outt[o] = xr[i] - se;
        }
    }
}

extern "C" void kernel_launch(void* const* d_in, const int* in_sizes, int n_in,
                              void* d_out, int out_size)
{
    const float* x  = (const float*)d_in[0];
    const float* bc = (const float*)d_in[1];
    const float* am = (const float*)d_in[2];
    float* out = (float*)d_out;

    const size_t smem = (size_t)SMEM_FLOATS * sizeof(float);   // ~142 KB
    cudaFuncSetAttribute(iir_filtfilt_kernel,
                         cudaFuncAttributeMaxDynamicSharedMemorySize, (int)smem);

    dim3 grid(Bsz * (Dd / SPB));   // 16 * 64 = 1024 blocks
    iir_filtfilt_kernel<<<grid, NTH, smem>>>(x, bc, am, out);
}

// round 2
// speedup vs baseline: 1.2448x; 1.2448x over previous
#include <cuda_runtime.h>

// Problem constants
#define Bsz   16
#define Lseq  4096
#define Dd    512
#define SPB   8          // d-lanes per block (32B sector granularity)
#define CH    32         // chunk length per thread
#define NCH   128        // chunks per sequence (CH*NCH == Lseq)
#define NTH   1024       // SPB * NCH
#define YSTR  33         // padded per-thread stride in Y (conflict-free)

// Dynamic smem (floats): Y + RR + MM + VV + SS + XE(=YE) + CV
#define SMEM_FLOATS (NTH*YSTR + 2*CH + 4 + 2*NTH + 2*NTH + 2*NTH + 16)

__global__ void __launch_bounds__(NTH, 1)
iir_filtfilt_kernel(const float* __restrict__ x,
                    const float* __restrict__ bc,
                    const float* __restrict__ am,
                    float* __restrict__ out)
{
    extern __shared__ float sm[];
    float*  Y  = sm;                               // NTH*YSTR : x, read back for trend
    float2* RR = (float2*)(Y + NTH * YSTR);        // CH : row0(A^(i+1))
    float*  MM = (float*)(RR + CH);                // 4  : A^CH
    float*  VV = MM + 4;                           // 2*NTH : chunk end-states
    float*  SS = VV + 2 * NTH;                     // 2*NTH : chunk start-states
    float*  XE = SS + 2 * NTH;                     // 2*NTH : x-edges, then y-edges
    float*  CV = XE + 2 * NTH;                     // 16 : fwd/bwd boundary constants

    const int tid = threadIdx.x;
    const int seq = tid & (SPB - 1);
    const int ch  = tid >> 3;                      // 0..127
    const int b   = blockIdx.x >> 6;
    const int d0  = (blockIdx.x & 63) * SPB;

    const float b0  = bc[0], b1 = bc[1], b2 = bc[2];
    const float na1 = am[0], na2 = am[1];          // A row0 = (-a1, -a2)
    const float bsum = b0 + b1 + b2;

    // Thread 0: RR[i] = row0(A^(i+1)), MM = A^CH.
    if (tid == 0) {
        float p00 = na1, p01 = na2, p10 = 1.f, p11 = 0.f;
        RR[0] = make_float2(p00, p01);
        for (int i = 1; i < CH; ++i) {
            float q00 = fmaf(na1, p00, na2 * p10);
            float q01 = fmaf(na1, p01, na2 * p11);
            p10 = p00; p11 = p01;
            p00 = q00; p01 = q01;
            RR[i] = make_float2(p00, p01);
        }
        MM[0] = p00; MM[1] = p01; MM[2] = p10; MM[3] = p11;
    }

    // Load own chunk straight to registers (coalesced 32B sectors per 8 lanes),
    // mirror into smem Y (single write pass; re-read only for trend at the end).
    const float* xp = x + ((size_t)b * Lseq + (size_t)ch * CH) * Dd + d0 + seq;
    float xr[CH];
    #pragma unroll
    for (int i = 0; i < CH; ++i) xr[i] = xp[(size_t)i * Dd];
    #pragma unroll
    for (int i = 0; i < CH; ++i) Y[tid * YSTR + i] = xr[i];
    XE[2 * tid]     = xr[CH - 2];                  // x halo for next chunk
    XE[2 * tid + 1] = xr[CH - 1];
    if (ch == 0) CV[seq] = bsum * xr[0];           // c_fwd = (b0+b1+b2)*x[0]
    __syncthreads();

    // Forward phase-1: zero-init scan, p0_fwd kept in registers (overwrites xr).
    float xm1, xm2;
    if (ch == 0) { xm1 = xr[0]; xm2 = xr[0]; }
    else         { xm1 = XE[2 * (tid - SPB) + 1]; xm2 = XE[2 * (tid - SPB)]; }

    float s0 = 0.f, s1 = 0.f;
    #pragma unroll
    for (int i = 0; i < CH; ++i) {
        float bx = fmaf(b2, xm2, fmaf(b1, xm1, b0 * xr[i]));
        xm2 = xm1; xm1 = xr[i];
        float ns = fmaf(na1, s0, fmaf(na2, s1, bx));
        s1 = s0; s0 = ns;
        xr[i] = ns;                                // now p0_fwd
    }
    VV[2 * tid] = s0; VV[2 * tid + 1] = s1;
    __syncthreads();

    // Forward chunk-combine (one thread per sequence, 128 steps).
    if (tid < SPB) {
        float m00 = MM[0], m01 = MM[1], m10 = MM[2], m11 = MM[3];
        float c = CV[tid], t0 = c, t1 = c;
        for (int j = 0; j < NCH; ++j) {
            int idx = 2 * (j * SPB + tid);
            float v0 = VV[idx], v1 = VV[idx + 1];
            SS[idx] = t0; SS[idx + 1] = t1;
            float u0 = fmaf(m00, t0, fmaf(m01, t1, v0));
            float u1 = fmaf(m10, t0, fmaf(m11, t1, v1));
            t0 = u0; t1 = u1;
        }
    }
    __syncthreads();

    // Publish y-edges (y[0], y[1] of each chunk) for backward halos;
    // fwd fix-up is otherwise fused into the backward scan.
    float ss0 = SS[2 * tid], ss1 = SS[2 * tid + 1];
    {
        float2 r0 = RR[0], r1 = RR[1];
        XE[2 * tid]     = fmaf(r0.x, ss0, fmaf(r0.y, ss1, xr[0]));
        XE[2 * tid + 1] = fmaf(r1.x, ss0, fmaf(r1.y, ss1, xr[1]));
        if (ch == NCH - 1) {
            float2 rl = RR[CH - 1];
            CV[SPB + seq] = bsum * fmaf(rl.x, ss0, fmaf(rl.y, ss1, xr[CH - 1]));
        }
    }
    __syncthreads();

    // Backward phase-1: reconstruct y on the fly (p0 + RR·ss), anticausal
    // zero-init scan; p0_bwd overwrites registers.
    float yp1, yp2;
    if (ch == NCH - 1) {
        float2 rl = RR[CH - 1];
        float e = fmaf(rl.x, ss0, fmaf(rl.y, ss1, xr[CH - 1]));
        yp1 = e; yp2 = e;                          // clamp at L-1
    } else {
        yp1 = XE[2 * (tid + SPB)];
        yp2 = XE[2 * (tid + SPB) + 1];
    }
    s0 = 0.f; s1 = 0.f;
    #pragma unroll
    for (int i = CH - 1; i >= 0; --i) {
        float2 r = RR[i];
        float yv = fmaf(r.x, ss0, fmaf(r.y, ss1, xr[i]));
        float bx = fmaf(b2, yp2, fmaf(b1, yp1, b0 * yv));
        yp2 = yp1; yp1 = yv;
        float ns = fmaf(na1, s0, fmaf(na2, s1, bx));
        s1 = s0; s0 = ns;
        xr[i] = ns;                                // now p0_bwd
    }
    VV[2 * tid] = s0; VV[2 * tid + 1] = s1;
    __syncthreads();

    // Backward chunk-combine (reversed).
    if (tid < SPB) {
        float m00 = MM[0], m01 = MM[1], m10 = MM[2], m11 = MM[3];
        float c = CV[SPB + tid], t0 = c, t1 = c;
        for (int j = NCH - 1; j >= 0; --j) {
            int idx = 2 * (j * SPB + tid);
            float v0 = VV[idx], v1 = VV[idx + 1];
            SS[idx] = t0; SS[idx + 1] = t1;
            float u0 = fmaf(m00, t0, fmaf(m01, t1, v0));
            float u1 = fmaf(m10, t0, fmaf(m11, t1, v1));
            t0 = u0; t1 = u1;
        }
    }
    __syncthreads();

    // Final fix-up + stores: seas = p0_bwd + RR[CH-1-i]·ss_b ; trend = x - seas.
    ss0 = SS[2 * tid]; ss1 = SS[2 * tid + 1];
    float* outs = out + ((size_t)b * Lseq + (size_t)ch * CH) * Dd + d0 + seq;
    float* outt = outs + (size_t)Bsz * Lseq * Dd;
    #pragma unroll
    for (int i = 0; i < CH; ++i) {
        float2 r = RR[CH - 1 - i];
        float se = fmaf(r.x, ss0, fmaf(r.y, ss1, xr[i]));
        outs[(size_t)i * Dd] = se;
        outt[(size_t)i * Dd] = Y[tid * YSTR + i] - se;
    }
}

extern "C" void kernel_launch(void* const* d_in, const int* in_sizes, int n_in,
                              void* d_out, int out_size)
{
    const float* x  = (const float*)d_in[0];
    const float* bc = (const float*)d_in[1];
    const float* am = (const float*)d_in[2];
    float* out = (float*)d_out;

    const size_t smem = (size_t)SMEM_FLOATS * sizeof(float);   // ~156 KB
    cudaFuncSetAttribute(iir_filtfilt_kernel,
                         cudaFuncAttributeMaxDynamicSharedMemorySize, (int)smem);

    dim3 grid(Bsz * (Dd / SPB));   // 1024 blocks
    iir_filtfilt_kernel<<<grid, NTH, smem>>>(x, bc, am, out);
}

// round 5
// speedup vs baseline: 1.4186x; 1.1396x over previous
#include <cuda_runtime.h>

// Problem constants
#define Bsz   16
#define Lseq  4096
#define Dd    512
#define SPB   8          // d-lanes per tile
#define CH    32         // chunk length per thread
#define NCH   128        // chunks per sequence
#define NTH   1024       // SPB * NCH
#define YSTR  33         // padded per-thread stride in Y
#define TILES (Bsz*(Dd/SPB))   // 1024

// smem floats: Y + RR + PW + VW + SW + XE + CV
#define SMEM_FLOATS (NTH*YSTR + 2*CH + 16 + 512 + 512 + 2*NTH + 16)

__global__ void __launch_bounds__(NTH, 1)
iir_filtfilt_kernel(const float* __restrict__ x,
                    const float* __restrict__ bc,
                    const float* __restrict__ am,
                    float* __restrict__ out)
{
    extern __shared__ float sm[];
    float*  Y  = sm;                               // NTH*YSTR : x copy (for trend)
    float2* RR = (float2*)(Y + NTH * YSTR);        // CH : row0(A^(i+1))
    float*  PW = (float*)(RR + CH);                // 16 : A^32,A^64,A^96,A^128 (2x2 each)
    float*  VW = PW + 16;                          // 512 : warp aggregates [w][seq][2]
    float*  SW = VW + 512;                         // 512 : warp start states
    float*  XE = SW + 512;                         // 2*NTH : x-halos then y-edges
    float*  CV = XE + 2 * NTH;                     // 16 : boundary constants

    const int tid  = threadIdx.x;
    const int lane = tid & 31;
    const int wrp  = tid >> 5;                     // 0..31
    const int seq  = tid & 7;
    const int ch   = tid >> 3;                     // 0..127
    const int g    = lane >> 3;                    // group offset 0..3 (== ch&3)

    const float b0  = bc[0], b1 = bc[1], b2 = bc[2];
    const float na1 = am[0], na2 = am[1];          // A row0 = (-a1,-a2)
    const float bsum = b0 + b1 + b2;

    // Thread 0: RR[i]=row0(A^(i+1)) and PW = {A^32, A^64, A^96, A^128}.
    if (tid == 0) {
        float p00 = na1, p01 = na2, p10 = 1.f, p11 = 0.f;
        RR[0] = make_float2(p00, p01);
        for (int i = 1; i < CH; ++i) {
            float q00 = fmaf(na1, p00, na2 * p10);
            float q01 = fmaf(na1, p01, na2 * p11);
            p10 = p00; p11 = p01; p00 = q00; p01 = q01;
            RR[i] = make_float2(p00, p01);
        }
        float a00 = p00, a01 = p01, a10 = p10, a11 = p11;   // A^32
        float c00 = a00, c01 = a01, c10 = a10, c11 = a11;
        PW[0] = c00; PW[1] = c01; PW[2] = c10; PW[3] = c11;
        for (int k = 1; k < 4; ++k) {
            float n00 = c00*a00 + c01*a10, n01 = c00*a01 + c01*a11;
            float n10 = c10*a00 + c11*a10, n11 = c10*a01 + c11*a11;
            c00 = n00; c01 = n01; c10 = n10; c11 = n11;
            PW[4*k] = c00; PW[4*k+1] = c01; PW[4*k+2] = c10; PW[4*k+3] = c11;
        }
    }

    const size_t OUTT = (size_t)Bsz * Lseq * Dd;

    for (int t = blockIdx.x; t < TILES; t += gridDim.x) {
        const int b  = t >> 6;
        const int d0 = (t & 63) * SPB;
        const float* xp = x + ((size_t)b * Lseq + (size_t)ch * CH) * Dd + d0 + seq;

        // Load own chunk to registers (4x 32B sectors / warp-instr, L2-hot after
        // the first tile thanks to prefetch).
        float xr[CH];
        #pragma unroll
        for (int i = 0; i < CH; ++i) xr[i] = xp[(size_t)i * Dd];

        __syncthreads();    // previous tile finished reading Y/XE/CV (B1)

        #pragma unroll
        for (int i = 0; i < CH; ++i) Y[tid * YSTR + i] = xr[i];
        XE[2 * tid]     = xr[CH - 2];
        XE[2 * tid + 1] = xr[CH - 1];
        if (ch == 0) CV[seq] = bsum * xr[0];
        __syncthreads();    // (B2)

        // Next-tile prefetch target (self-prefetch on last tile: harmless).
        int t2 = t + gridDim.x;  if (t2 >= TILES) t2 = t;
        const float* xpn = x + ((size_t)(t2 >> 6) * Lseq + (size_t)ch * CH) * Dd
                             + ((t2 & 63) * SPB) + seq;

        // ---------------- forward zero-init scan (p0 -> xr) ------------------
        float xm1, xm2;
        if (ch == 0) { xm1 = xr[0]; xm2 = xr[0]; }
        else         { xm1 = XE[2*(tid-SPB)+1]; xm2 = XE[2*(tid-SPB)]; }
        float s0 = 0.f, s1 = 0.f;
        #pragma unroll
        for (int i = 0; i < CH; ++i) {
            asm volatile("prefetch.global.L2 [%0];" :: "l"(xpn + (size_t)i * Dd));
            float bx = fmaf(b2, xm2, fmaf(b1, xm1, b0 * xr[i]));
            xm2 = xm1; xm1 = xr[i];
            float ns = fmaf(na1, s0, fmaf(na2, s1, bx));
            s1 = s0; s0 = ns;
            xr[i] = ns;
        }

        // Intra-warp aggregate over the warp's 4 chunks per sequence.
        // E_g = sum_{k<g} M^(g-1-k) v_k  (M = A^32), V_w = v_3 + M*E_3.
        float va0 = __shfl_up_sync(0xffffffffu, s0, 8);
        float va1 = __shfl_up_sync(0xffffffffu, s1, 8);
        float vb0 = __shfl_up_sync(0xffffffffu, s0, 16);
        float vb1 = __shfl_up_sync(0xffffffffu, s1, 16);
        float vc0 = __shfl_up_sync(0xffffffffu, s0, 24);
        float vc1 = __shfl_up_sync(0xffffffffu, s1, 24);
        if (g < 1) { va0 = 0.f; va1 = 0.f; }
        if (g < 2) { vb0 = 0.f; vb1 = 0.f; }
        if (g < 3) { vc0 = 0.f; vc1 = 0.f; }
        float E0, E1;
        {
            float m00 = PW[0], m01 = PW[1], m10 = PW[2], m11 = PW[3];   // A^32
            float w00 = PW[4], w01 = PW[5], w10 = PW[6], w11 = PW[7];   // A^64
            E0 = va0 + m00*vb0 + m01*vb1 + w00*vc0 + w01*vc1;
            E1 = va1 + m10*vb0 + m11*vb1 + w10*vc0 + w11*vc1;
            if (g == 3) {
                int idx = 2 * (wrp * 8 + seq);
                VW[idx]     = fmaf(m00, E0, fmaf(m01, E1, s0));
                VW[idx + 1] = fmaf(m10, E0, fmaf(m11, E1, s1));
            }
        }
        __syncthreads();    // (B3)

        // Serial combine over 32 warp aggregates (one thread per sequence).
        if (tid < SPB) {
            float g00 = PW[12], g01 = PW[13], g10 = PW[14], g11 = PW[15]; // A^128
            float c = CV[tid], t0 = c, t1 = c;
            for (int w = 0; w < 32; ++w) {
                int idx = 2 * (w * 8 + tid);
                SW[idx] = t0; SW[idx + 1] = t1;
                float v0 = VW[idx], v1 = VW[idx + 1];
                float u0 = fmaf(g00, t0, fmaf(g01, t1, v0));
                float u1 = fmaf(g10, t0, fmaf(g11, t1, v1));
                t0 = u0; t1 = u1;
            }
        }
        __syncthreads();    // (B4)

        // Per-thread forward start state: ss = M^g * T_w + E_g.
        float ss0, ss1;
        {
            int idx = 2 * (wrp * 8 + seq);
            float T0 = SW[idx], T1 = SW[idx + 1];
            if (g == 0) { ss0 = T0; ss1 = T1; }
            else {
                const float* P = PW + 4 * (g - 1);
                ss0 = fmaf(P[0], T0, fmaf(P[1], T1, E0));
                ss1 = fmaf(P[2], T0, fmaf(P[3], T1, E1));
            }
        }

        // Publish y-edges (y0,y1) for the backward halos; c_bwd from y[L-1].
        {
            float2 r0 = RR[0], r1 = RR[1];
            XE[2 * tid]     = fmaf(r0.x, ss0, fmaf(r0.y, ss1, xr[0]));
            XE[2 * tid + 1] = fmaf(r1.x, ss0, fmaf(r1.y, ss1, xr[1]));
            if (ch == NCH - 1) {
                float2 rl = RR[CH - 1];
                CV[SPB + seq] = bsum * fmaf(rl.x, ss0, fmaf(rl.y, ss1, xr[CH - 1]));
            }
        }
        __syncthreads();    // (B5)

        // ---------------- backward zero-init scan (p0_bwd -> xr) -------------
        float yp1, yp2;
        if (ch == NCH - 1) {
            float2 rl = RR[CH - 1];
            float e = fmaf(rl.x, ss0, fmaf(rl.y, ss1, xr[CH - 1]));
            yp1 = e; yp2 = e;
        } else {
            yp1 = XE[2 * (tid + SPB)];
            yp2 = XE[2 * (tid + SPB) + 1];
        }
        s0 = 0.f; s1 = 0.f;
        #pragma unroll
        for (int i = CH - 1; i >= 0; --i) {
            float2 r = RR[i];
            float yv = fmaf(r.x, ss0, fmaf(r.y, ss1, xr[i]));
            float bx = fmaf(b2, yp2, fmaf(b1, yp1, b0 * yv));
            yp2 = yp1; yp1 = yv;
            float ns = fmaf(na1, s0, fmaf(na2, s1, bx));
            s1 = s0; s0 = ns;
            xr[i] = ns;
        }

        // Backward intra-warp aggregate (descending chunk order).
        va0 = __shfl_down_sync(0xffffffffu, s0, 8);
        va1 = __shfl_down_sync(0xffffffffu, s1, 8);
        vb0 = __shfl_down_sync(0xffffffffu, s0, 16);
        vb1 = __shfl_down_sync(0xffffffffu, s1, 16);
        vc0 = __shfl_down_sync(0xffffffffu, s0, 24);
        vc1 = __shfl_down_sync(0xffffffffu, s1, 24);
        if (g > 2) { va0 = 0.f; va1 = 0.f; }
        if (g > 1) { vb0 = 0.f; vb1 = 0.f; }
        if (g > 0) { vc0 = 0.f; vc1 = 0.f; }
        {
            float m00 = PW[0], m01 = PW[1], m10 = PW[2], m11 = PW[3];
            float w00 = PW[4], w01 = PW[5], w10 = PW[6], w11 = PW[7];
            E0 = va0 + m00*vb0 + m01*vb1 + w00*vc0 + w01*vc1;
            E1 = va1 + m10*vb0 + m11*vb1 + w10*vc0 + w11*vc1;
            if (g == 0) {
                int idx = 2 * (wrp * 8 + seq);
                VW[idx]     = fmaf(m00, E0, fmaf(m01, E1, s0));
                VW[idx + 1] = fmaf(m10, E0, fmaf(m11, E1, s1));
            }
        }
        __syncthreads();    // (B6)

        if (tid < SPB) {
            float g00 = PW[12], g01 = PW[13], g10 = PW[14], g11 = PW[15];
            float c = CV[SPB + tid], t0 = c, t1 = c;
            for (int w = 31; w >= 0; --w) {
                int idx = 2 * (w * 8 + tid);
                SW[idx] = t0; SW[idx + 1] = t1;
                float v0 = VW[idx], v1 = VW[idx + 1];
                float u0 = fmaf(g00, t0, fmaf(g01, t1, v0));
                float u1 = fmaf(g10, t0, fmaf(g11, t1, v1));
                t0 = u0; t1 = u1;
            }
        }
        __syncthreads();    // (B7)

        // Backward start state: sb = M^(3-g) * T'_w + E'_g.
        float sb0, sb1;
        {
            int idx = 2 * (wrp * 8 + seq);
            float T0 = SW[idx], T1 = SW[idx + 1];
            if (g == 3) { sb0 = T0; sb1 = T1; }
            else {
                const float* P = PW + 4 * (2 - g);
                sb0 = fmaf(P[0], T0, fmaf(P[1], T1, E0));
                sb1 = fmaf(P[2], T0, fmaf(P[3], T1, E1));
            }
        }

        // Final fix-up + streaming stores.
        float* os = out + ((size_t)b * Lseq + (size_t)ch * CH) * Dd + d0 + seq;
        float* ot = os + OUTT;
        #pragma unroll
        for (int i = 0; i < CH; ++i) {
            float2 r = RR[CH - 1 - i];
            float se = fmaf(r.x, sb0, fmaf(r.y, sb1, xr[i]));
            __stcs(os + (size_t)i * Dd, se);
            __stcs(ot + (size_t)i * Dd, Y[tid * YSTR + i] - se);
        }
    }
}

extern "C" void kernel_launch(void* const* d_in, const int* in_sizes, int n_in,
                              void* d_out, int out_size)
{
    const float* x  = (const float*)d_in[0];
    const float* bc = (const float*)d_in[1];
    const float* am = (const float*)d_in[2];
    float* out = (float*)d_out;

    int dev = 0;
    cudaGetDevice(&dev);
    int sms = 148;
    cudaDeviceGetAttribute(&sms, cudaDevAttrMultiProcessorCount, dev);
    if (sms > TILES) sms = TILES;

    const size_t smem = (size_t)SMEM_FLOATS * sizeof(float);   // ~144 KB
    cudaFuncSetAttribute(iir_filtfilt_kernel,
                         cudaFuncAttributeMaxDynamicSharedMemorySize, (int)smem);

    iir_filtfilt_kernel<<<sms, NTH, smem>>>(x, bc, am, out);
}